// round 11
// baseline (speedup 1.0000x reference)
#include <cuda_runtime.h>
#include <cuda_bf16.h>
#include <math.h>
#include <stdint.h>

// x: (8,4096,512) -> N=32768, D=512 ; embed: (1,8192,512) -> C=8192
// Outputs (float32, concatenated in d_out):
//   quantize 16,777,216 | embed_ind 32,768 | new_embed 4,194,304 | new_cs 8,192

#define N_TOK   32768
#define C_CODES 8192
#define D_DIM   512
#define ONE_MINUS_DECAY 0.2f
#define CAND_THR 1.0e-2f
#define TOPK 8

// -------- device scratch ----------------------------------------------------
__device__ float          g_embed_n[C_CODES * D_DIM];   // normalized codebook fp32
__device__ float          g_xn[N_TOK * D_DIM];          // normalized tokens fp32
__device__ __nv_bfloat16  g_en_b[C_CODES * D_DIM];      // bf16 codebook
__device__ __nv_bfloat16  g_xn_b[N_TOK * D_DIM];        // bf16 tokens
__device__ float          g_embed_sum[C_CODES * D_DIM];
__device__ float          g_bins[C_CODES];
__device__ int            g_ind[N_TOK];
__device__ float          g_candv[N_TOK * 32];          // 4 sublists x 8 per row
__device__ int            g_candi[N_TOK * 32];

// -------- helpers -----------------------------------------------------------
__device__ __forceinline__ uint32_t smem_u32(const void* p) {
    uint32_t a;
    asm("{ .reg .u64 t; cvta.to.shared.u64 t, %1; cvt.u32.u64 %0, t; }"
        : "=r"(a) : "l"(p));
    return a;
}

__device__ __forceinline__ float block_reduce_sum_128(float v) {
    #pragma unroll
    for (int o = 16; o > 0; o >>= 1) v += __shfl_xor_sync(0xffffffffu, v, o);
    __shared__ float sp[4];
    int w = threadIdx.x >> 5, l = threadIdx.x & 31;
    if (l == 0) sp[w] = v;
    __syncthreads();
    if (threadIdx.x == 0) sp[0] = sp[0] + sp[1] + sp[2] + sp[3];
    __syncthreads();
    return sp[0];
}

// Reference-faithful sum of squares (XLA:CPU aarch64 VF=4 IC=2 order).
__device__ __forceinline__ float mimic_sumsq_512(const float* __restrict__ s) {
    float p0 = 0.f, p1 = 0.f, p2 = 0.f, p3 = 0.f;
    float p4 = 0.f, p5 = 0.f, p6 = 0.f, p7 = 0.f;
    #pragma unroll 4
    for (int j = 0; j < D_DIM; j += 8) {
        p0 = fmaf(s[j + 0], s[j + 0], p0);
        p1 = fmaf(s[j + 1], s[j + 1], p1);
        p2 = fmaf(s[j + 2], s[j + 2], p2);
        p3 = fmaf(s[j + 3], s[j + 3], p3);
        p4 = fmaf(s[j + 4], s[j + 4], p4);
        p5 = fmaf(s[j + 5], s[j + 5], p5);
        p6 = fmaf(s[j + 6], s[j + 6], p6);
        p7 = fmaf(s[j + 7], s[j + 7], p7);
    }
    float v0 = p0 + p4, v1 = p1 + p5, v2 = p2 + p6, v3 = p3 + p7;
    return (v0 + v2) + (v1 + v3);
}

// Exact sequential-k fp32 chain (identical order to the R5-passing GEMM).
__device__ __forceinline__ float exact_dot(int row, int c) {
    const float4* xa = reinterpret_cast<const float4*>(g_xn + (size_t)row * D_DIM);
    const float4* eb = reinterpret_cast<const float4*>(g_embed_n + (size_t)c * D_DIM);
    float acc = 0.f;
    #pragma unroll 8
    for (int k = 0; k < D_DIM / 4; k++) {
        float4 a = xa[k], b = eb[k];
        acc = fmaf(a.x, b.x, acc);
        acc = fmaf(a.y, b.y, acc);
        acc = fmaf(a.z, b.z, acc);
        acc = fmaf(a.w, b.w, acc);
    }
    return acc;
}

// ============================================================================
// Kernel 1: normalize codebook (fp32 div, clip) + bf16 copy + zero scatter.
// ============================================================================
__global__ void norm_embed_kernel(const float* __restrict__ embed) {
    __shared__ float srow[D_DIM];
    __shared__ float s_norm;
    int c = blockIdx.x, t = threadIdx.x;
    float4 e = reinterpret_cast<const float4*>(embed + (size_t)c * D_DIM)[t];
    reinterpret_cast<float4*>(srow)[t] = e;
    __syncthreads();
    if (t == 0) {
        float nrm = sqrtf(mimic_sumsq_512(srow));
        if (nrm < 1e-12f) nrm = 1e-12f;
        s_norm = nrm;
    }
    __syncthreads();
    float nrm = s_norm;
    float4 en = make_float4(__fdiv_rn(e.x, nrm), __fdiv_rn(e.y, nrm),
                            __fdiv_rn(e.z, nrm), __fdiv_rn(e.w, nrm));
    reinterpret_cast<float4*>(g_embed_n + (size_t)c * D_DIM)[t] = en;
    __nv_bfloat162 b0 = __floats2bfloat162_rn(en.x, en.y);
    __nv_bfloat162 b1 = __floats2bfloat162_rn(en.z, en.w);
    *reinterpret_cast<__nv_bfloat162*>(g_en_b + (size_t)c * D_DIM + t * 4) = b0;
    *reinterpret_cast<__nv_bfloat162*>(g_en_b + (size_t)c * D_DIM + t * 4 + 2) = b1;
    reinterpret_cast<float4*>(g_embed_sum + (size_t)c * D_DIM)[t] =
        make_float4(0.f, 0.f, 0.f, 0.f);
    if (t == 0) g_bins[c] = 0.f;
}

// ============================================================================
// Kernel 1b: normalize tokens + bf16 copy.
// ============================================================================
__global__ void norm_x_kernel(const float* __restrict__ X) {
    __shared__ float srow[D_DIM];
    __shared__ float s_norm;
    int n = blockIdx.x, t = threadIdx.x;
    float4 xv = reinterpret_cast<const float4*>(X + (size_t)n * D_DIM)[t];
    reinterpret_cast<float4*>(srow)[t] = xv;
    __syncthreads();
    if (t == 0) {
        float nrm = sqrtf(mimic_sumsq_512(srow));
        if (nrm < 1e-12f) nrm = 1e-12f;
        s_norm = nrm;
    }
    __syncthreads();
    float nrm = s_norm;
    float4 xn = make_float4(__fdiv_rn(xv.x, nrm), __fdiv_rn(xv.y, nrm),
                            __fdiv_rn(xv.z, nrm), __fdiv_rn(xv.w, nrm));
    reinterpret_cast<float4*>(g_xn + (size_t)n * D_DIM)[t] = xn;
    __nv_bfloat162 b0 = __floats2bfloat162_rn(xn.x, xn.y);
    __nv_bfloat162 b1 = __floats2bfloat162_rn(xn.z, xn.w);
    *reinterpret_cast<__nv_bfloat162*>(g_xn_b + (size_t)n * D_DIM + t * 4) = b0;
    *reinterpret_cast<__nv_bfloat162*>(g_xn_b + (size_t)n * D_DIM + t * 4 + 2) = b1;
}

// ============================================================================
// Kernel 2: bf16 mma.sync GEMM + per-row approx top-8 candidates.
// 256 threads (8 warps). Warp w owns rows [16w, 16w+16) of the CTA's 128 rows.
// A (128x512 bf16) resident in smem, row stride 520 bf16 (1040 B).
// B streamed: 512 chunks of (128 codes x 64 K) via cp.async, double-buffered,
// row stride 72 bf16 (144 B). Warp tile 16x128 = 16 mma(m16n8k16) per k-step.
// ============================================================================
#define GT_THREADS 256
#define A_STRIDE_B 1040              // 520 bf16
#define B_STRIDE_B 144               // 72 bf16
#define A_BYTES    (128 * A_STRIDE_B)          // 133120
#define B_BYTES    (128 * B_STRIDE_B)          // 18432
#define SM_TOT     (A_BYTES + 2 * B_BYTES)     // 169984

__device__ __forceinline__ void mma16816(float* d, uint32_t a0, uint32_t a1,
                                         uint32_t a2, uint32_t a3,
                                         uint32_t b0, uint32_t b1) {
    asm volatile(
        "mma.sync.aligned.m16n8k16.row.col.f32.bf16.bf16.f32 "
        "{%0,%1,%2,%3}, {%4,%5,%6,%7}, {%8,%9}, {%0,%1,%2,%3};"
        : "+f"(d[0]), "+f"(d[1]), "+f"(d[2]), "+f"(d[3])
        : "r"(a0), "r"(a1), "r"(a2), "r"(a3), "r"(b0), "r"(b1));
}

__device__ __forceinline__ void topk_upd(float* tv, int* ti, float& tmin,
                                         float v, int c) {
    if (v > tmin) {
        int ms = 0;
        float mv = tv[0];
        #pragma unroll
        for (int q = 1; q < TOPK; q++)
            if (tv[q] < mv) { mv = tv[q]; ms = q; }
        tv[ms] = v; ti[ms] = c;
        mv = tv[0];
        #pragma unroll
        for (int q = 1; q < TOPK; q++) mv = fminf(mv, tv[q]);
        tmin = mv;
    }
}

__global__ __launch_bounds__(GT_THREADS, 1)
void gemm_topk_kernel() {
    extern __shared__ __align__(128) unsigned char smem[];
    const uint32_t sA = smem_u32(smem);
    const uint32_t sB = sA + A_BYTES;
    const int tid = threadIdx.x;
    const int w = tid >> 5;
    const int l = tid & 31;
    const int rowBase = blockIdx.x * 128;

    // ---- load resident A (128 x 512 bf16), padded rows -----------------------
    for (int i = 0; i < 32; i++) {
        int idx = tid + i * GT_THREADS;      // 8192 segs of 16B
        int row = idx >> 6, seg = idx & 63;
        uint4 v = *reinterpret_cast<const uint4*>(
            g_xn_b + (size_t)(rowBase + row) * D_DIM + seg * 8);
        *reinterpret_cast<uint4*>(smem + row * A_STRIDE_B + seg * 16) = v;
    }

    // per-thread ldmatrix base addresses
    const uint32_t aAddr = sA + (uint32_t)(16 * w + (l & 15)) * A_STRIDE_B
                         + (uint32_t)(l >> 4) * 16;
    const uint32_t bThr  = (uint32_t)(((l >> 4) * 8 + (l & 7)) * B_STRIDE_B)
                         + (uint32_t)((l >> 3) & 1) * 16;

    float acc[16][4];
    #pragma unroll
    for (int nt = 0; nt < 16; nt++)
        #pragma unroll
        for (int q = 0; q < 4; q++) acc[nt][q] = 0.f;

    float t0v[TOPK], t1v[TOPK];
    int   t0i[TOPK], t1i[TOPK];
    #pragma unroll
    for (int q = 0; q < TOPK; q++) {
        t0v[q] = -3.4e38f; t1v[q] = -3.4e38f; t0i[q] = 0; t1i[q] = 0;
    }
    float tmin0 = -3.4e38f, tmin1 = -3.4e38f;

    // B chunk loader: chunk g -> codes [(g/8)*128, +128), K [(g%8)*64, +64)
    auto load_chunk = [&](int g, int buf) {
        const __nv_bfloat16* src =
            g_en_b + (size_t)((g >> 3) * 128) * D_DIM + (g & 7) * 64;
        uint32_t dst0 = sB + buf * B_BYTES;
        #pragma unroll
        for (int i = 0; i < 4; i++) {
            int idx = tid + i * GT_THREADS;  // 1024 segs of 16B
            int row = idx >> 3, seg = idx & 7;
            uint32_t dst = dst0 + row * B_STRIDE_B + seg * 16;
            const void* sp = src + (size_t)row * D_DIM + seg * 8;
            asm volatile("cp.async.cg.shared.global [%0], [%1], 16;"
                         :: "r"(dst), "l"(sp));
        }
        asm volatile("cp.async.commit_group;" ::: "memory");
    };

    load_chunk(0, 0);

    for (int g = 0; g < 512; g++) {
        const int buf = g & 1;
        if (g + 1 < 512) {
            load_chunk(g + 1, buf ^ 1);
            asm volatile("cp.async.wait_group 1;" ::: "memory");
        } else {
            asm volatile("cp.async.wait_group 0;" ::: "memory");
        }
        __syncthreads();

        const uint32_t kchunk = (uint32_t)(g & 7) * 128;   // byte offset in A row
        const uint32_t bBase = sB + buf * B_BYTES + bThr;
        #pragma unroll
        for (int ks = 0; ks < 4; ks++) {
            uint32_t a0, a1, a2, a3;
            asm volatile("ldmatrix.sync.aligned.m8n8.x4.shared.b16 "
                         "{%0,%1,%2,%3}, [%4];"
                         : "=r"(a0), "=r"(a1), "=r"(a2), "=r"(a3)
                         : "r"(aAddr + kchunk + ks * 32));
            #pragma unroll
            for (int p = 0; p < 8; p++) {
                uint32_t b0, b1, b2, b3;
                asm volatile("ldmatrix.sync.aligned.m8n8.x4.shared.b16 "
                             "{%0,%1,%2,%3}, [%4];"
                             : "=r"(b0), "=r"(b1), "=r"(b2), "=r"(b3)
                             : "r"(bBase + p * (16 * B_STRIDE_B) + ks * 32));
                mma16816(acc[2 * p],     a0, a1, a2, a3, b0, b1);
                mma16816(acc[2 * p + 1], a0, a1, a2, a3, b2, b3);
            }
        }

        if ((g & 7) == 7) {
            // fold this 128-col tile into per-row top-8, re-zero acc
            const int colBase = (g >> 3) * 128;
            #pragma unroll
            for (int nt = 0; nt < 16; nt++) {
                const int c0 = colBase + nt * 8 + 2 * (l & 3);
                topk_upd(t0v, t0i, tmin0, acc[nt][0], c0);
                topk_upd(t0v, t0i, tmin0, acc[nt][1], c0 + 1);
                topk_upd(t1v, t1i, tmin1, acc[nt][2], c0);
                topk_upd(t1v, t1i, tmin1, acc[nt][3], c0 + 1);
                acc[nt][0] = 0.f; acc[nt][1] = 0.f;
                acc[nt][2] = 0.f; acc[nt][3] = 0.f;
            }
        }
        __syncthreads();
    }

    // dump candidates: rows r0 = rowBase+16w+(l>>2), r1 = r0+8; sublist (l&3)
    const int r0 = rowBase + 16 * w + (l >> 2);
    const int r1 = r0 + 8;
    const int s0 = (l & 3) * TOPK;
    #pragma unroll
    for (int q = 0; q < TOPK; q++) {
        g_candv[(size_t)r0 * 32 + s0 + q] = t0v[q];
        g_candi[(size_t)r0 * 32 + s0 + q] = t0i[q];
        g_candv[(size_t)r1 * 32 + s0 + q] = t1v[q];
        g_candi[(size_t)r1 * 32 + s0 + q] = t1i[q];
    }
}

// ============================================================================
// Kernel 2b: resolve — pick candidates within thr of approx max, rescore
// exactly (R5 chain), first-index tie-break. Sublist-truncation suspicion
// (sublist min >= cut) triggers full exact row scan (rare).
// ============================================================================
__global__ void resolve_kernel() {
    int r = blockIdx.x * 128 + threadIdx.x;
    if (r >= N_TOK) return;
    float cv[32]; int ci[32];
    #pragma unroll
    for (int q = 0; q < 32; q++) {
        cv[q] = g_candv[(size_t)r * 32 + q];
        ci[q] = g_candi[(size_t)r * 32 + q];
    }
    float M = cv[0];
    #pragma unroll
    for (int q = 1; q < 32; q++) M = fmaxf(M, cv[q]);
    float cut = M - CAND_THR;

    bool suspicious = false;
    #pragma unroll
    for (int s = 0; s < 4; s++) {
        float mn = cv[s * TOPK];
        #pragma unroll
        for (int q = 1; q < TOPK; q++) mn = fminf(mn, cv[s * TOPK + q]);
        if (mn >= cut) suspicious = true;
    }

    if (suspicious) {
        float bev = -3.4e38f; int bi = 0;
        for (int c = 0; c < C_CODES; c++) {
            float v = exact_dot(r, c);
            if (v > bev) { bev = v; bi = c; }
        }
        g_ind[r] = bi;
        return;
    }

    int cand[32]; int nc = 0;
    #pragma unroll
    for (int q = 0; q < 32; q++)
        if (cv[q] >= cut) cand[nc++] = ci[q];

    if (nc == 1) { g_ind[r] = cand[0]; return; }

    float bev = -3.4e38f; int bi = 0x7fffffff;
    for (int q = 0; q < nc; q++) {
        float v = exact_dot(r, cand[q]);
        if (v > bev || (v == bev && cand[q] < bi)) { bev = v; bi = cand[q]; }
    }
    g_ind[r] = bi;
}

// ============================================================================
// Kernel 3: per-token epilogue (gather quantize, scatter normalized x + bins).
// ============================================================================
__global__ void epilogue_kernel(const float* __restrict__ embed,
                                float* __restrict__ out_q,
                                float* __restrict__ out_ind) {
    int n = blockIdx.x, t = threadIdx.x;
    int c = g_ind[n];
    float4 xn = reinterpret_cast<const float4*>(g_xn + (size_t)n * D_DIM)[t];
    float* es = g_embed_sum + (size_t)c * D_DIM + t * 4;
    atomicAdd(es + 0, xn.x);
    atomicAdd(es + 1, xn.y);
    atomicAdd(es + 2, xn.z);
    atomicAdd(es + 3, xn.w);
    float4 ev = reinterpret_cast<const float4*>(embed + (size_t)c * D_DIM)[t];
    reinterpret_cast<float4*>(out_q + (size_t)n * D_DIM)[t] = ev;
    if (t == 0) {
        out_ind[n] = (float)c;
        atomicAdd(&g_bins[c], 1.0f);
    }
}

// ============================================================================
// Kernel 4: per-code EMA finalize.
// ============================================================================
__global__ void finalize_kernel(const float* __restrict__ embed,
                                const float* __restrict__ cluster_size,
                                float* __restrict__ out_embed,
                                float* __restrict__ out_cs) {
    int c = blockIdx.x, t = threadIdx.x;
    float b = g_bins[c];
    bool zero = (b == 0.0f);
    float inv_b = 1.0f / (zero ? 1.0f : b);
    float4 es = reinterpret_cast<const float4*>(g_embed_sum + (size_t)c * D_DIM)[t];
    float4 v = make_float4(es.x * inv_b, es.y * inv_b, es.z * inv_b, es.w * inv_b);
    float ss = v.x * v.x + v.y * v.y + v.z * v.z + v.w * v.w;
    ss = block_reduce_sum_128(ss);
    float rn = 1.0f / fmaxf(sqrtf(ss), 1e-12f);
    float4 en;
    if (zero) en = reinterpret_cast<const float4*>(g_embed_n + (size_t)c * D_DIM)[t];
    else      en = make_float4(v.x * rn, v.y * rn, v.z * rn, v.w * rn);
    float4 e = reinterpret_cast<const float4*>(embed + (size_t)c * D_DIM)[t];
    reinterpret_cast<float4*>(out_embed + (size_t)c * D_DIM)[t] =
        make_float4(e.x + ONE_MINUS_DECAY * (en.x - e.x),
                    e.y + ONE_MINUS_DECAY * (en.y - e.y),
                    e.z + ONE_MINUS_DECAY * (en.z - e.z),
                    e.w + ONE_MINUS_DECAY * (en.w - e.w));
    if (t == 0) {
        float cs = cluster_size[c];
        out_cs[c] = cs + ONE_MINUS_DECAY * (b - cs);
    }
}

// ============================================================================
extern "C" void kernel_launch(void* const* d_in, const int* in_sizes, int n_in,
                              void* d_out, int out_size) {
    const float* x     = (const float*)d_in[0];
    const float* embed = (const float*)d_in[1];
    const float* cs    = (const float*)d_in[2];

    float* out       = (float*)d_out;
    float* out_q     = out;
    float* out_ind   = out + 16777216;
    float* out_embed = out + 16777216 + 32768;
    float* out_cs    = out + 16777216 + 32768 + 4194304;

    cudaFuncSetAttribute(gemm_topk_kernel,
                         cudaFuncAttributeMaxDynamicSharedMemorySize, SM_TOT);

    norm_embed_kernel<<<C_CODES, 128>>>(embed);
    norm_x_kernel<<<N_TOK, 128>>>(x);
    gemm_topk_kernel<<<N_TOK / 128, GT_THREADS, SM_TOT>>>();
    resolve_kernel<<<N_TOK / 128, 128>>>();
    epilogue_kernel<<<N_TOK, 128>>>(embed, out_q, out_ind);
    finalize_kernel<<<C_CODES, 128>>>(embed, cs, out_embed, out_cs);
}

// round 12
// speedup vs baseline: 8.6803x; 8.6803x over previous
#include <cuda_runtime.h>
#include <math.h>
#include <stdint.h>

// x: (8,4096,512) -> N=32768, D=512 ; embed: (1,8192,512) -> C=8192
// Outputs (float32, concatenated in d_out):
//   quantize 16,777,216 | embed_ind 32,768 | new_embed 4,194,304 | new_cs 8,192

#define N_TOK   32768
#define C_CODES 8192
#define D_DIM   512
#define DW      128              // D_DIM/4 int32 words of packed int8
#define ONE_MINUS_DECAY 0.2f
#define CAND_THR 1.2e-2f

// -------- device scratch ----------------------------------------------------
__device__ float g_embed_n[C_CODES * D_DIM];   // normalized codebook fp32
__device__ float g_xn[N_TOK * D_DIM];          // normalized tokens fp32
__device__ int   g_eq[C_CODES * DW];           // int8-packed codebook
__device__ int   g_xq[N_TOK * DW];             // int8-packed tokens
__device__ float g_es[C_CODES];                // codebook scales (amax/127)
__device__ float g_xs[N_TOK];                  // token scales
__device__ float g_embed_sum[C_CODES * D_DIM];
__device__ float g_bins[C_CODES];
__device__ int   g_ind[N_TOK];
__device__ float g_candv[N_TOK * 48];          // 16 thr x (v1,v2,v3)
__device__ int   g_candi[N_TOK * 32];          // 16 thr x (i1,i2)
__device__ int   g_hard[N_TOK];
__device__ int   g_n_hard;

// -------- helpers -----------------------------------------------------------
__device__ __forceinline__ float block_reduce_sum_128(float v) {
    #pragma unroll
    for (int o = 16; o > 0; o >>= 1) v += __shfl_xor_sync(0xffffffffu, v, o);
    __shared__ float sp[4];
    int w = threadIdx.x >> 5, l = threadIdx.x & 31;
    if (l == 0) sp[w] = v;
    __syncthreads();
    if (threadIdx.x == 0) sp[0] = sp[0] + sp[1] + sp[2] + sp[3];
    __syncthreads();
    return sp[0];
}

__device__ __forceinline__ float block_reduce_max_128(float v) {
    #pragma unroll
    for (int o = 16; o > 0; o >>= 1)
        v = fmaxf(v, __shfl_xor_sync(0xffffffffu, v, o));
    __shared__ float mp[4];
    int w = threadIdx.x >> 5, l = threadIdx.x & 31;
    if (l == 0) mp[w] = v;
    __syncthreads();
    if (threadIdx.x == 0)
        mp[0] = fmaxf(fmaxf(mp[0], mp[1]), fmaxf(mp[2], mp[3]));
    __syncthreads();
    return mp[0];
}

// Reference-faithful sum of squares (XLA:CPU aarch64 VF=4 IC=2 order).
__device__ __forceinline__ float mimic_sumsq_512(const float* __restrict__ s) {
    float p0 = 0.f, p1 = 0.f, p2 = 0.f, p3 = 0.f;
    float p4 = 0.f, p5 = 0.f, p6 = 0.f, p7 = 0.f;
    #pragma unroll 4
    for (int j = 0; j < D_DIM; j += 8) {
        p0 = fmaf(s[j + 0], s[j + 0], p0);
        p1 = fmaf(s[j + 1], s[j + 1], p1);
        p2 = fmaf(s[j + 2], s[j + 2], p2);
        p3 = fmaf(s[j + 3], s[j + 3], p3);
        p4 = fmaf(s[j + 4], s[j + 4], p4);
        p5 = fmaf(s[j + 5], s[j + 5], p5);
        p6 = fmaf(s[j + 6], s[j + 6], p6);
        p7 = fmaf(s[j + 7], s[j + 7], p7);
    }
    float v0 = p0 + p4, v1 = p1 + p5, v2 = p2 + p6, v3 = p3 + p7;
    return (v0 + v2) + (v1 + v3);
}

// Exact sequential-k fp32 chain (identical order to the R5-passing GEMM).
__device__ __forceinline__ float exact_dot(int row, int c) {
    const float4* xa = reinterpret_cast<const float4*>(g_xn + (size_t)row * D_DIM);
    const float4* eb = reinterpret_cast<const float4*>(g_embed_n + (size_t)c * D_DIM);
    float acc = 0.f;
    #pragma unroll 8
    for (int k = 0; k < D_DIM / 4; k++) {
        float4 a = xa[k], b = eb[k];
        acc = fmaf(a.x, b.x, acc);
        acc = fmaf(a.y, b.y, acc);
        acc = fmaf(a.z, b.z, acc);
        acc = fmaf(a.w, b.w, acc);
    }
    return acc;
}

__device__ __forceinline__ int pack_q4(float4 v, float inv_s) {
    int q0 = __float2int_rn(v.x * inv_s);
    int q1 = __float2int_rn(v.y * inv_s);
    int q2 = __float2int_rn(v.z * inv_s);
    int q3 = __float2int_rn(v.w * inv_s);
    return (q0 & 255) | ((q1 & 255) << 8) | ((q2 & 255) << 16) | (q3 << 24);
}

// ============================================================================
// Kernel 1: normalize codebook (fp32 div, clip) + int8 quantize + zero bufs.
// ============================================================================
__global__ void norm_embed_kernel(const float* __restrict__ embed) {
    __shared__ float srow[D_DIM];
    __shared__ float s_norm;
    int c = blockIdx.x, t = threadIdx.x;
    float4 e = reinterpret_cast<const float4*>(embed + (size_t)c * D_DIM)[t];
    reinterpret_cast<float4*>(srow)[t] = e;
    __syncthreads();
    if (t == 0) {
        float nrm = sqrtf(mimic_sumsq_512(srow));
        if (nrm < 1e-12f) nrm = 1e-12f;
        s_norm = nrm;
    }
    __syncthreads();
    float nrm = s_norm;
    float4 en = make_float4(__fdiv_rn(e.x, nrm), __fdiv_rn(e.y, nrm),
                            __fdiv_rn(e.z, nrm), __fdiv_rn(e.w, nrm));
    reinterpret_cast<float4*>(g_embed_n + (size_t)c * D_DIM)[t] = en;

    float am = fmaxf(fmaxf(fabsf(en.x), fabsf(en.y)),
                     fmaxf(fabsf(en.z), fabsf(en.w)));
    am = block_reduce_max_128(am);
    float s = (am > 0.f) ? (am / 127.f) : 1.f;
    g_eq[(size_t)c * DW + t] = pack_q4(en, 1.f / s);
    if (t == 0) {
        g_es[c] = s;
        g_bins[c] = 0.f;
        if (c == 0) g_n_hard = 0;
    }
    reinterpret_cast<float4*>(g_embed_sum + (size_t)c * D_DIM)[t] =
        make_float4(0.f, 0.f, 0.f, 0.f);
}

// ============================================================================
// Kernel 1b: normalize tokens + int8 quantize.
// ============================================================================
__global__ void norm_x_kernel(const float* __restrict__ X) {
    __shared__ float srow[D_DIM];
    __shared__ float s_norm;
    int n = blockIdx.x, t = threadIdx.x;
    float4 xv = reinterpret_cast<const float4*>(X + (size_t)n * D_DIM)[t];
    reinterpret_cast<float4*>(srow)[t] = xv;
    __syncthreads();
    if (t == 0) {
        float nrm = sqrtf(mimic_sumsq_512(srow));
        if (nrm < 1e-12f) nrm = 1e-12f;
        s_norm = nrm;
    }
    __syncthreads();
    float nrm = s_norm;
    float4 xn = make_float4(__fdiv_rn(xv.x, nrm), __fdiv_rn(xv.y, nrm),
                            __fdiv_rn(xv.z, nrm), __fdiv_rn(xv.w, nrm));
    reinterpret_cast<float4*>(g_xn + (size_t)n * D_DIM)[t] = xn;

    float am = fmaxf(fmaxf(fabsf(xn.x), fabsf(xn.y)),
                     fmaxf(fabsf(xn.z), fabsf(xn.w)));
    am = block_reduce_max_128(am);
    float s = (am > 0.f) ? (am / 127.f) : 1.f;
    g_xq[(size_t)n * DW + t] = pack_q4(xn, 1.f / s);
    if (t == 0) g_xs[n] = s;
}

// ============================================================================
// Kernel 2: int8 dp4a GEMM + per-row candidate top-lists.
// Structure mirrors the R5-passing fp32 GEMM: BM=BN=128, BK=16 int32 words
// (=64 int8 K-elems), 256 thr, 8x8 microtile. 8 k-tiles cover K'=128 words.
// Fold per coltile: vf = (float)acc * s_b[col]; per-thread per-row top-2
// (values+idx) + v3 sentinel for overflow detection.
// ============================================================================
#define BM 128
#define BN 128
#define BKW 16

__global__ __launch_bounds__(256, 2)
void gemm_cand_kernel() {
    __shared__ int   As[BKW][BM];
    __shared__ int   Bs[BKW][BN];
    __shared__ float s_bs[BN];

    const int tid  = threadIdx.x;
    const int tcol = tid & 15;
    const int trow = tid >> 4;
    const int m0 = trow * 8;
    const int n0 = tcol * 8;
    const int rowBase = blockIdx.x * BM;
    const int* __restrict__ XQ = g_xq;
    const int* __restrict__ EQ = g_eq;

    const int lr = tid >> 2;          // 0..63
    const int lc = (tid & 3) * 4;     // 0,4,8,12

    float v1[8], v2[8], v3[8];
    int   i1[8], i2[8];
    #pragma unroll
    for (int i = 0; i < 8; i++) {
        v1[i] = -3.4e38f; v2[i] = -3.4e38f; v3[i] = -3.4e38f;
        i1[i] = 0; i2[i] = 0;
    }

    for (int nt = 0; nt < C_CODES / BN; nt++) {
        const int colBase = nt * BN;
        __syncthreads();                       // previous fold done with s_bs
        if (tid < BN) s_bs[tid] = g_es[colBase + tid];

        int acc[8][8];
        #pragma unroll
        for (int i = 0; i < 8; i++)
            #pragma unroll
            for (int j = 0; j < 8; j++) acc[i][j] = 0;

        for (int kt = 0; kt < DW / BKW; kt++) {
            const int k0 = kt * BKW;
            {
                const int* p0 = XQ + (size_t)(rowBase + lr) * DW + k0 + lc;
                const int* p1 = p0 + (size_t)64 * DW;
                int4 a0 = *reinterpret_cast<const int4*>(p0);
                int4 a1 = *reinterpret_cast<const int4*>(p1);
                As[lc + 0][lr] = a0.x; As[lc + 1][lr] = a0.y;
                As[lc + 2][lr] = a0.z; As[lc + 3][lr] = a0.w;
                As[lc + 0][lr + 64] = a1.x; As[lc + 1][lr + 64] = a1.y;
                As[lc + 2][lr + 64] = a1.z; As[lc + 3][lr + 64] = a1.w;
            }
            {
                const int* p0 = EQ + (size_t)(colBase + lr) * DW + k0 + lc;
                const int* p1 = p0 + (size_t)64 * DW;
                int4 b0 = *reinterpret_cast<const int4*>(p0);
                int4 b1 = *reinterpret_cast<const int4*>(p1);
                Bs[lc + 0][lr] = b0.x; Bs[lc + 1][lr] = b0.y;
                Bs[lc + 2][lr] = b0.z; Bs[lc + 3][lr] = b0.w;
                Bs[lc + 0][lr + 64] = b1.x; Bs[lc + 1][lr + 64] = b1.y;
                Bs[lc + 2][lr + 64] = b1.z; Bs[lc + 3][lr + 64] = b1.w;
            }
            __syncthreads();

            #pragma unroll
            for (int k = 0; k < BKW; k++) {
                int4 a0 = *reinterpret_cast<const int4*>(&As[k][m0]);
                int4 a1 = *reinterpret_cast<const int4*>(&As[k][m0 + 4]);
                int4 b0 = *reinterpret_cast<const int4*>(&Bs[k][n0]);
                int4 b1 = *reinterpret_cast<const int4*>(&Bs[k][n0 + 4]);
                int a[8] = {a0.x, a0.y, a0.z, a0.w, a1.x, a1.y, a1.z, a1.w};
                int b[8] = {b0.x, b0.y, b0.z, b0.w, b1.x, b1.y, b1.z, b1.w};
                #pragma unroll
                for (int i = 0; i < 8; i++)
                    #pragma unroll
                    for (int j = 0; j < 8; j++)
                        acc[i][j] = __dp4a(a[i], b[j], acc[i][j]);
            }
            __syncthreads();
        }

        // fold tile (j ascending -> earlier code index wins ties)
        #pragma unroll
        for (int j = 0; j < 8; j++) {
            const int c = colBase + n0 + j;
            const float sc = s_bs[n0 + j];
            #pragma unroll
            for (int i = 0; i < 8; i++) {
                float vf = (float)acc[i][j] * sc;
                if (vf > v1[i]) {
                    v3[i] = v2[i]; v2[i] = v1[i]; i2[i] = i1[i];
                    v1[i] = vf; i1[i] = c;
                } else if (vf > v2[i]) {
                    v3[i] = v2[i]; v2[i] = vf; i2[i] = c;
                } else if (vf > v3[i]) {
                    v3[i] = vf;
                }
            }
        }
    }

    #pragma unroll
    for (int i = 0; i < 8; i++) {
        const int r = rowBase + m0 + i;
        g_candv[(size_t)r * 48 + tcol * 3 + 0] = v1[i];
        g_candv[(size_t)r * 48 + tcol * 3 + 1] = v2[i];
        g_candv[(size_t)r * 48 + tcol * 3 + 2] = v3[i];
        g_candi[(size_t)r * 32 + tcol * 2 + 0] = i1[i];
        g_candi[(size_t)r * 32 + tcol * 2 + 1] = i2[i];
    }
}

// ============================================================================
// Kernel 2b: resolve. approx values v are in units of s_a (v = s_b * I), so
// cut = M - CAND_THR / s_a. Rows where any thread's v3 >= cut may have hidden
// candidates -> appended to hard list for full exact scan.
// ============================================================================
__global__ void resolve_pick_kernel() {
    int r = blockIdx.x * 128 + threadIdx.x;
    if (r >= N_TOK) return;
    float v[48]; int ci[32];
    #pragma unroll
    for (int q = 0; q < 48; q++) v[q] = g_candv[(size_t)r * 48 + q];
    #pragma unroll
    for (int q = 0; q < 32; q++) ci[q] = g_candi[(size_t)r * 32 + q];

    float M = -3.4e38f;
    #pragma unroll
    for (int t = 0; t < 16; t++) M = fmaxf(M, v[t * 3]);
    float cut = M - CAND_THR / g_xs[r];

    bool flag = false;
    #pragma unroll
    for (int t = 0; t < 16; t++)
        if (v[t * 3 + 2] >= cut) flag = true;
    if (flag) {
        int slot = atomicAdd(&g_n_hard, 1);
        g_hard[slot] = r;
        return;
    }

    int cand[32]; int nc = 0;
    #pragma unroll
    for (int t = 0; t < 16; t++) {
        if (v[t * 3 + 0] >= cut) cand[nc++] = ci[t * 2 + 0];
        if (v[t * 3 + 1] >= cut) cand[nc++] = ci[t * 2 + 1];
    }
    if (nc == 1) { g_ind[r] = cand[0]; return; }

    float bev = -3.4e38f; int bi = 0x7fffffff;
    for (int q = 0; q < nc; q++) {
        float d = exact_dot(r, cand[q]);
        if (d > bev || (d == bev && cand[q] < bi)) { bev = d; bi = cand[q]; }
    }
    g_ind[r] = bi;
}

// Full exact scan for flagged rows: one block per list entry (strided).
__global__ __launch_bounds__(256, 4)
void resolve_hard_kernel() {
    __shared__ float s_v[256];
    __shared__ int   s_i[256];
    const int nh = g_n_hard;
    for (int it = blockIdx.x; it < nh; it += gridDim.x) {
        const int r = g_hard[it];
        float bv = -3.4e38f; int bi = 0x7fffffff;
        for (int c = threadIdx.x; c < C_CODES; c += 256) {
            float d = exact_dot(r, c);
            if (d > bv) { bv = d; bi = c; }     // ascending c -> first idx
        }
        s_v[threadIdx.x] = bv; s_i[threadIdx.x] = bi;
        __syncthreads();
        for (int s = 128; s > 0; s >>= 1) {
            if (threadIdx.x < s) {
                float ov = s_v[threadIdx.x + s]; int oi = s_i[threadIdx.x + s];
                if (ov > s_v[threadIdx.x] ||
                    (ov == s_v[threadIdx.x] && oi < s_i[threadIdx.x])) {
                    s_v[threadIdx.x] = ov; s_i[threadIdx.x] = oi;
                }
            }
            __syncthreads();
        }
        if (threadIdx.x == 0) g_ind[r] = s_i[0];
        __syncthreads();
    }
}

// ============================================================================
// Kernel 3: per-token epilogue (gather quantize, scatter normalized x + bins).
// ============================================================================
__global__ void epilogue_kernel(const float* __restrict__ embed,
                                float* __restrict__ out_q,
                                float* __restrict__ out_ind) {
    int n = blockIdx.x, t = threadIdx.x;
    int c = g_ind[n];
    float4 xn = reinterpret_cast<const float4*>(g_xn + (size_t)n * D_DIM)[t];
    float* es = g_embed_sum + (size_t)c * D_DIM + t * 4;
    atomicAdd(es + 0, xn.x);
    atomicAdd(es + 1, xn.y);
    atomicAdd(es + 2, xn.z);
    atomicAdd(es + 3, xn.w);
    float4 ev = reinterpret_cast<const float4*>(embed + (size_t)c * D_DIM)[t];
    reinterpret_cast<float4*>(out_q + (size_t)n * D_DIM)[t] = ev;
    if (t == 0) {
        out_ind[n] = (float)c;
        atomicAdd(&g_bins[c], 1.0f);
    }
}

// ============================================================================
// Kernel 4: per-code EMA finalize.
// ============================================================================
__global__ void finalize_kernel(const float* __restrict__ embed,
                                const float* __restrict__ cluster_size,
                                float* __restrict__ out_embed,
                                float* __restrict__ out_cs) {
    int c = blockIdx.x, t = threadIdx.x;
    float b = g_bins[c];
    bool zero = (b == 0.0f);
    float inv_b = 1.0f / (zero ? 1.0f : b);
    float4 es = reinterpret_cast<const float4*>(g_embed_sum + (size_t)c * D_DIM)[t];
    float4 v = make_float4(es.x * inv_b, es.y * inv_b, es.z * inv_b, es.w * inv_b);
    float ss = v.x * v.x + v.y * v.y + v.z * v.z + v.w * v.w;
    ss = block_reduce_sum_128(ss);
    float rn = 1.0f / fmaxf(sqrtf(ss), 1e-12f);
    float4 en;
    if (zero) en = reinterpret_cast<const float4*>(g_embed_n + (size_t)c * D_DIM)[t];
    else      en = make_float4(v.x * rn, v.y * rn, v.z * rn, v.w * rn);
    float4 e = reinterpret_cast<const float4*>(embed + (size_t)c * D_DIM)[t];
    reinterpret_cast<float4*>(out_embed + (size_t)c * D_DIM)[t] =
        make_float4(e.x + ONE_MINUS_DECAY * (en.x - e.x),
                    e.y + ONE_MINUS_DECAY * (en.y - e.y),
                    e.z + ONE_MINUS_DECAY * (en.z - e.z),
                    e.w + ONE_MINUS_DECAY * (en.w - e.w));
    if (t == 0) {
        float cs = cluster_size[c];
        out_cs[c] = cs + ONE_MINUS_DECAY * (b - cs);
    }
}

// ============================================================================
extern "C" void kernel_launch(void* const* d_in, const int* in_sizes, int n_in,
                              void* d_out, int out_size) {
    const float* x     = (const float*)d_in[0];
    const float* embed = (const float*)d_in[1];
    const float* cs    = (const float*)d_in[2];

    float* out       = (float*)d_out;
    float* out_q     = out;
    float* out_ind   = out + 16777216;
    float* out_embed = out + 16777216 + 32768;
    float* out_cs    = out + 16777216 + 32768 + 4194304;

    norm_embed_kernel<<<C_CODES, 128>>>(embed);
    norm_x_kernel<<<N_TOK, 128>>>(x);
    gemm_cand_kernel<<<N_TOK / BM, 256>>>();
    resolve_pick_kernel<<<N_TOK / 128, 128>>>();
    resolve_hard_kernel<<<148, 256>>>();
    epilogue_kernel<<<N_TOK, 128>>>(embed, out_q, out_ind);
    finalize_kernel<<<C_CODES, 128>>>(embed, cs, out_embed, out_cs);
}